// round 1
// baseline (speedup 1.0000x reference)
#include <cuda_runtime.h>
#include <math.h>
#include <stdint.h>

// Problem constants
#define VOCAB   32000
#define EMBED   512
#define HIDDEN  1024
#define G4      4096
#define BATCH   64
#define SRCLEN  1024
#define NCTA    128

// Scratch (device globals: allocation-free rule)
__device__ float    d_xproj[(size_t)SRCLEN * BATCH * G4];  // (t, b, g) fp32, 1 GB
__device__ float    d_h[2][BATCH * HIDDEN];                // double-buffered hidden
__device__ unsigned d_bar[SRCLEN];                          // per-step barrier counters

// ---------------------------------------------------------------------------
// init: zero h[0] and barrier counters (runs on every graph replay)
// ---------------------------------------------------------------------------
__global__ void init_kernel() {
    int i = blockIdx.x * blockDim.x + threadIdx.x;
    if (i < BATCH * HIDDEN) d_h[0][i] = 0.0f;
    if (i < SRCLEN)         d_bar[i]  = 0u;
}

// ---------------------------------------------------------------------------
// x_proj: x_proj[t][b][g] = emb[src[b][t]] . Wx[g] + bx[g]
// GEMM M=65536 (m = t*64+b), N=4096, K=512. BM=BN=128, BK=8, 256 thr, 8x8 tile.
// ---------------------------------------------------------------------------
__global__ void __launch_bounds__(256) xproj_kernel(
    const int* __restrict__ src, const float* __restrict__ emb,
    const float* __restrict__ Wx, const float* __restrict__ bx)
{
    __shared__ float A_sm[8][132];
    __shared__ float B_sm[8][132];
    __shared__ int   tok[128];

    const int tid = threadIdx.x;
    const int bm0 = blockIdx.y * 128;
    const int bn0 = blockIdx.x * 128;

    if (tid < 128) {
        int m = bm0 + tid;
        tok[tid] = src[(m & 63) * SRCLEN + (m >> 6)];
    }
    __syncthreads();

    const int lr = tid >> 1;          // staged row 0..127
    const int lk = (tid & 1) << 2;    // k offset 0 or 4
    const int tm = tid & 15;          // 8-row group
    const int tn = tid >> 4;          // 8-col group

    float acc[8][8];
#pragma unroll
    for (int i = 0; i < 8; i++)
#pragma unroll
        for (int j = 0; j < 8; j++) acc[i][j] = 0.0f;

    const float* embA = emb + (size_t)tok[lr] * EMBED + lk;
    const float* WxB  = Wx  + (size_t)(bn0 + lr) * EMBED + lk;

    for (int k0 = 0; k0 < EMBED; k0 += 8) {
        float4 av = *(const float4*)(embA + k0);
        float4 bv = *(const float4*)(WxB  + k0);
        __syncthreads();
        A_sm[lk + 0][lr] = av.x; A_sm[lk + 1][lr] = av.y;
        A_sm[lk + 2][lr] = av.z; A_sm[lk + 3][lr] = av.w;
        B_sm[lk + 0][lr] = bv.x; B_sm[lk + 1][lr] = bv.y;
        B_sm[lk + 2][lr] = bv.z; B_sm[lk + 3][lr] = bv.w;
        __syncthreads();
#pragma unroll
        for (int kk = 0; kk < 8; kk++) {
            float4 a0 = *(const float4*)&A_sm[kk][tm * 8];
            float4 a1 = *(const float4*)&A_sm[kk][tm * 8 + 4];
            float4 b0 = *(const float4*)&B_sm[kk][tn * 8];
            float4 b1 = *(const float4*)&B_sm[kk][tn * 8 + 4];
            float a[8] = {a0.x, a0.y, a0.z, a0.w, a1.x, a1.y, a1.z, a1.w};
            float b[8] = {b0.x, b0.y, b0.z, b0.w, b1.x, b1.y, b1.z, b1.w};
#pragma unroll
            for (int i = 0; i < 8; i++)
#pragma unroll
                for (int j = 0; j < 8; j++) acc[i][j] += a[i] * b[j];
        }
    }

    float4 bb0 = __ldg((const float4*)(bx + bn0 + tn * 8));
    float4 bb1 = __ldg((const float4*)(bx + bn0 + tn * 8 + 4));
    float bb[8] = {bb0.x, bb0.y, bb0.z, bb0.w, bb1.x, bb1.y, bb1.z, bb1.w};

#pragma unroll
    for (int i = 0; i < 8; i++) {
        int m = bm0 + tm * 8 + i;
        float* dst = d_xproj + (size_t)m * G4 + bn0 + tn * 8;
        float4 o0 = make_float4(acc[i][0] + bb[0], acc[i][1] + bb[1],
                                acc[i][2] + bb[2], acc[i][3] + bb[3]);
        float4 o1 = make_float4(acc[i][4] + bb[4], acc[i][5] + bb[5],
                                acc[i][6] + bb[6], acc[i][7] + bb[7]);
        *(float4*)(dst)     = o0;
        *(float4*)(dst + 4) = o1;
    }
}

// ---------------------------------------------------------------------------
// Recurrence: 128 persistent CTAs (1/SM). CTA c owns hidden cols [c*8, c*8+8)
// -> 32 gate columns (4 gates x 8). Wh slice transposed in SMEM.
// Per step: gates = x_proj[t] + h_{t-1} @ Wh_slice^T (K split over 2 thread
// groups), gated elementwise, h written to L2 (st.cg), grid spin-barrier.
// ---------------------------------------------------------------------------
#define WT_STRIDE 36     // 32 cols + pad, 16B-aligned rows, conflict-free
#define HST_STRIDE 68    // 64 b + pad, 16B-aligned rows

__global__ void __launch_bounds__(256) lstm_kernel(
    const float* __restrict__ Wh, float* __restrict__ out)
{
    extern __shared__ float sm[];
    float* Wt  = sm;                         // 1024*36   = 36864 floats
    float* hst = sm + 36864;                 // 2*64*68   = 8704 floats
    float* csm = sm + 36864 + 8704;          // 64*8      = 512 floats
    float* red = hst;                        // reuse: 128*16 = 2048
    float* gsm = hst + 2048;                 // reuse: 64*32  = 2048

    const int tid = threadIdx.x;
    const int cta = blockIdx.x;

    // Load Wh slice transposed: Wt[k*36 + lc], lc = gate*8 + jloc
    for (int i = tid; i < 32 * HIDDEN; i += 256) {
        int lc = i & 31;
        int k  = i >> 5;
        int grow = (lc >> 3) * HIDDEN + cta * 8 + (lc & 7);
        Wt[k * WT_STRIDE + lc] = Wh[(size_t)grow * HIDDEN + k];
    }
    for (int i = tid; i < 512; i += 256) csm[i] = 0.0f;
    __syncthreads();

    const int gh = tid >> 7;       // K-half group (0: k<512, 1: k>=512)
    const int r  = tid & 127;
    const int tm = r & 15;         // batch group: rows tm*4..tm*4+3
    const int tn = r >> 4;         // gate-col group: lc tn*4..tn*4+3

    for (int t = 0; t < SRCLEN; t++) {
        const float* hprev = d_h[t & 1];
        float*       hnext = d_h[(t + 1) & 1];

        // Prefetch this step's x_proj slice early (independent of h)
        float4 xr[4];
        if (gh == 0) {
            int lc = tn * 4;
            int gcol = (lc >> 3) * HIDDEN + cta * 8 + (lc & 7);
#pragma unroll
            for (int i = 0; i < 4; i++) {
                int b = tm * 4 + i;
                xr[i] = __ldg((const float4*)(d_xproj +
                              ((size_t)t * BATCH + b) * G4 + gcol));
            }
        }

        float acc[4][4];
#pragma unroll
        for (int i = 0; i < 4; i++)
#pragma unroll
            for (int j = 0; j < 4; j++) acc[i][j] = 0.0f;

        for (int kc = 0; kc < 8; kc++) {
            // Stage h chunks (64 k per group) transposed: hst[g][k][b]
            float4 v[8];
#pragma unroll
            for (int it = 0; it < 8; it++) {
                int q  = tid + it * 256;        // 0..2047
                int g  = q >> 10;
                int b  = (q & 1023) >> 4;
                int kq = q & 15;
                int kglob = g * 512 + kc * 64 + kq * 4;
                v[it] = __ldcg((const float4*)(hprev + b * HIDDEN + kglob));
            }
            __syncthreads();
#pragma unroll
            for (int it = 0; it < 8; it++) {
                int q  = tid + it * 256;
                int g  = q >> 10;
                int b  = (q & 1023) >> 4;
                int kq = q & 15;
                float* dp = hst + g * (64 * HST_STRIDE) + (kq * 4) * HST_STRIDE + b;
                dp[0]              = v[it].x;
                dp[HST_STRIDE]     = v[it].y;
                dp[2 * HST_STRIDE] = v[it].z;
                dp[3 * HST_STRIDE] = v[it].w;
            }
            __syncthreads();

            const float* hs    = hst + gh * (64 * HST_STRIDE) + tm * 4;
            const float* wbase = Wt + (gh * 512 + kc * 64) * WT_STRIDE + tn * 4;
#pragma unroll 8
            for (int kk = 0; kk < 64; kk++) {
                float4 h4 = *(const float4*)(hs + kk * HST_STRIDE);
                float4 w4 = *(const float4*)(wbase + kk * WT_STRIDE);
                float ha[4] = {h4.x, h4.y, h4.z, h4.w};
                float wa[4] = {w4.x, w4.y, w4.z, w4.w};
#pragma unroll
                for (int i = 0; i < 4; i++)
#pragma unroll
                    for (int j = 0; j < 4; j++) acc[i][j] += ha[i] * wa[j];
            }
        }

        // Reduce K halves: group 1 -> smem, group 0 adds + builds gates
        __syncthreads();
        if (gh == 1) {
            float* rp = red + r * 16;
#pragma unroll
            for (int i = 0; i < 4; i++)
#pragma unroll
                for (int j = 0; j < 4; j++) rp[i * 4 + j] = acc[i][j];
        }
        __syncthreads();
        if (gh == 0) {
            const float* rp = red + r * 16;
#pragma unroll
            for (int i = 0; i < 4; i++) {
                int b = tm * 4 + i;
                float gx[4] = {xr[i].x, xr[i].y, xr[i].z, xr[i].w};
#pragma unroll
                for (int j = 0; j < 4; j++) {
                    gsm[b * 32 + tn * 4 + j] = acc[i][j] + rp[i * 4 + j] + gx[j];
                }
            }
        }
        __syncthreads();

        // Elementwise gates (reference order: i, f, o, g)
        {
            int pidx = tid * 2;
#pragma unroll
            for (int e = 0; e < 2; e++, pidx++) {
                int b  = pidx >> 3;
                int jl = pidx & 7;
                float gi = gsm[b * 32 + jl];
                float gf = gsm[b * 32 + 8 + jl];
                float go = gsm[b * 32 + 16 + jl];
                float gg = gsm[b * 32 + 24 + jl];
                float ig = 1.0f / (1.0f + expf(-gi));
                float fg = 1.0f / (1.0f + expf(-gf));
                float og = 1.0f / (1.0f + expf(-go));
                float cg = tanhf(gg);
                float c  = fg * csm[b * 8 + jl] + ig * cg;
                float h  = og * tanhf(c);
                csm[b * 8 + jl] = c;
                int col = cta * 8 + jl;
                __stcg(hnext + b * HIDDEN + col, h);
                if (t == SRCLEN - 1) {
                    out[b * HIDDEN + col] = h;
                    out[BATCH * HIDDEN + b * HIDDEN + col] = c;
                }
            }
        }

        // Grid barrier (monotonic per-step counters; release via L2)
        __threadfence();
        __syncthreads();
        if (tid == 0) {
            atomicAdd(&d_bar[t], 1u);
            while (*((volatile unsigned*)&d_bar[t]) < (unsigned)NCTA) { }
        }
        __syncthreads();
    }
}

// ---------------------------------------------------------------------------
extern "C" void kernel_launch(void* const* d_in, const int* in_sizes, int n_in,
                              void* d_out, int out_size)
{
    const int*   src = (const int*)d_in[0];
    const float* emb = (const float*)d_in[1];
    const float* Wx  = (const float*)d_in[2];
    const float* bx  = (const float*)d_in[3];
    const float* Wh  = (const float*)d_in[4];
    float*       out = (float*)d_out;

    init_kernel<<<257, 256>>>();
    xproj_kernel<<<dim3(G4 / 128, (SRCLEN * BATCH) / 128), 256>>>(src, emb, Wx, bx);

    size_t smem_bytes = (size_t)(36864 + 8704 + 512) * sizeof(float); // 184320 B
    cudaFuncSetAttribute(lstm_kernel, cudaFuncAttributeMaxDynamicSharedMemorySize,
                         (int)smem_bytes);
    lstm_kernel<<<NCTA, 256, smem_bytes>>>(Wh, out);
}

// round 2
// speedup vs baseline: 1.0013x; 1.0013x over previous
#include <cuda_runtime.h>
#include <math.h>
#include <stdint.h>

// Problem constants
#define VOCAB   32000
#define EMBED   512
#define HIDDEN  1024
#define G4      4096
#define BATCH   64
#define SRCLEN  1024
#define NCTA    128

// Scratch (device globals: allocation-free rule)
__device__ float    d_xproj[(size_t)SRCLEN * BATCH * G4];  // (t, b, g) fp32, 1 GB
__device__ float    d_h[2][BATCH * HIDDEN];                // double-buffered hidden
__device__ unsigned d_bar[SRCLEN];                          // per-step barrier counters

// ---------------------------------------------------------------------------
// init: zero h[0] and barrier counters (runs on every graph replay)
// ---------------------------------------------------------------------------
__global__ void init_kernel() {
    int i = blockIdx.x * blockDim.x + threadIdx.x;
    if (i < BATCH * HIDDEN) d_h[0][i] = 0.0f;
    if (i < SRCLEN)         d_bar[i]  = 0u;
}

// ---------------------------------------------------------------------------
// x_proj: x_proj[t][b][g] = emb[src[b][t]] . Wx[g] + bx[g]
// GEMM M=65536 (m = t*64+b), N=4096, K=512. BM=BN=128, BK=8, 256 thr, 8x8 tile.
// ---------------------------------------------------------------------------
__global__ void __launch_bounds__(256) xproj_kernel(
    const int* __restrict__ src, const float* __restrict__ emb,
    const float* __restrict__ Wx, const float* __restrict__ bx)
{
    __shared__ float A_sm[8][132];
    __shared__ float B_sm[8][132];
    __shared__ int   tok[128];

    const int tid = threadIdx.x;
    const int bm0 = blockIdx.y * 128;
    const int bn0 = blockIdx.x * 128;

    if (tid < 128) {
        int m = bm0 + tid;
        tok[tid] = src[(m & 63) * SRCLEN + (m >> 6)];
    }
    __syncthreads();

    const int lr = tid >> 1;          // staged row 0..127
    const int lk = (tid & 1) << 2;    // k offset 0 or 4
    const int tm = tid & 15;          // 8-row group
    const int tn = tid >> 4;          // 8-col group

    float acc[8][8];
#pragma unroll
    for (int i = 0; i < 8; i++)
#pragma unroll
        for (int j = 0; j < 8; j++) acc[i][j] = 0.0f;

    const float* embA = emb + (size_t)tok[lr] * EMBED + lk;
    const float* WxB  = Wx  + (size_t)(bn0 + lr) * EMBED + lk;

    for (int k0 = 0; k0 < EMBED; k0 += 8) {
        float4 av = *(const float4*)(embA + k0);
        float4 bv = *(const float4*)(WxB  + k0);
        __syncthreads();
        A_sm[lk + 0][lr] = av.x; A_sm[lk + 1][lr] = av.y;
        A_sm[lk + 2][lr] = av.z; A_sm[lk + 3][lr] = av.w;
        B_sm[lk + 0][lr] = bv.x; B_sm[lk + 1][lr] = bv.y;
        B_sm[lk + 2][lr] = bv.z; B_sm[lk + 3][lr] = bv.w;
        __syncthreads();
#pragma unroll
        for (int kk = 0; kk < 8; kk++) {
            float4 a0 = *(const float4*)&A_sm[kk][tm * 8];
            float4 a1 = *(const float4*)&A_sm[kk][tm * 8 + 4];
            float4 b0 = *(const float4*)&B_sm[kk][tn * 8];
            float4 b1 = *(const float4*)&B_sm[kk][tn * 8 + 4];
            float a[8] = {a0.x, a0.y, a0.z, a0.w, a1.x, a1.y, a1.z, a1.w};
            float b[8] = {b0.x, b0.y, b0.z, b0.w, b1.x, b1.y, b1.z, b1.w};
#pragma unroll
            for (int i = 0; i < 8; i++)
#pragma unroll
                for (int j = 0; j < 8; j++) acc[i][j] += a[i] * b[j];
        }
    }

    float4 bb0 = __ldg((const float4*)(bx + bn0 + tn * 8));
    float4 bb1 = __ldg((const float4*)(bx + bn0 + tn * 8 + 4));
    float bb[8] = {bb0.x, bb0.y, bb0.z, bb0.w, bb1.x, bb1.y, bb1.z, bb1.w};

#pragma unroll
    for (int i = 0; i < 8; i++) {
        int m = bm0 + tm * 8 + i;
        float* dst = d_xproj + (size_t)m * G4 + bn0 + tn * 8;
        float4 o0 = make_float4(acc[i][0] + bb[0], acc[i][1] + bb[1],
                                acc[i][2] + bb[2], acc[i][3] + bb[3]);
        float4 o1 = make_float4(acc[i][4] + bb[4], acc[i][5] + bb[5],
                                acc[i][6] + bb[6], acc[i][7] + bb[7]);
        *(float4*)(dst)     = o0;
        *(float4*)(dst + 4) = o1;
    }
}

// ---------------------------------------------------------------------------
// Recurrence: 128 persistent CTAs (1/SM). CTA c owns hidden cols [c*8, c*8+8)
// -> 32 gate columns (4 gates x 8). Wh slice transposed in SMEM.
// Per step: gates = x_proj[t] + h_{t-1} @ Wh_slice^T (K split over 2 thread
// groups), gated elementwise, h written to L2 (st.cg), grid spin-barrier.
// ---------------------------------------------------------------------------
#define WT_STRIDE 36     // 32 cols + pad, 16B-aligned rows, conflict-free
#define HST_STRIDE 68    // 64 b + pad, 16B-aligned rows

__global__ void __launch_bounds__(256) lstm_kernel(
    const float* __restrict__ Wh, float* __restrict__ out)
{
    extern __shared__ float sm[];
    float* Wt  = sm;                         // 1024*36   = 36864 floats
    float* hst = sm + 36864;                 // 2*64*68   = 8704 floats
    float* csm = sm + 36864 + 8704;          // 64*8      = 512 floats
    float* red = hst;                        // reuse: 128*16 = 2048
    float* gsm = hst + 2048;                 // reuse: 64*32  = 2048

    const int tid = threadIdx.x;
    const int cta = blockIdx.x;

    // Load Wh slice transposed: Wt[k*36 + lc], lc = gate*8 + jloc
    for (int i = tid; i < 32 * HIDDEN; i += 256) {
        int lc = i & 31;
        int k  = i >> 5;
        int grow = (lc >> 3) * HIDDEN + cta * 8 + (lc & 7);
        Wt[k * WT_STRIDE + lc] = Wh[(size_t)grow * HIDDEN + k];
    }
    for (int i = tid; i < 512; i += 256) csm[i] = 0.0f;
    __syncthreads();

    const int gh = tid >> 7;       // K-half group (0: k<512, 1: k>=512)
    const int r  = tid & 127;
    const int tm = r & 15;         // batch group: rows tm*4..tm*4+3
    const int tn = r >> 4;         // gate-col group: lc tn*4..tn*4+3

    for (int t = 0; t < SRCLEN; t++) {
        const float* hprev = d_h[t & 1];
        float*       hnext = d_h[(t + 1) & 1];

        // Prefetch this step's x_proj slice early (independent of h)
        float4 xr[4];
        if (gh == 0) {
            int lc = tn * 4;
            int gcol = (lc >> 3) * HIDDEN + cta * 8 + (lc & 7);
#pragma unroll
            for (int i = 0; i < 4; i++) {
                int b = tm * 4 + i;
                xr[i] = __ldg((const float4*)(d_xproj +
                              ((size_t)t * BATCH + b) * G4 + gcol));
            }
        }

        float acc[4][4];
#pragma unroll
        for (int i = 0; i < 4; i++)
#pragma unroll
            for (int j = 0; j < 4; j++) acc[i][j] = 0.0f;

        for (int kc = 0; kc < 8; kc++) {
            // Stage h chunks (64 k per group) transposed: hst[g][k][b]
            float4 v[8];
#pragma unroll
            for (int it = 0; it < 8; it++) {
                int q  = tid + it * 256;        // 0..2047
                int g  = q >> 10;
                int b  = (q & 1023) >> 4;
                int kq = q & 15;
                int kglob = g * 512 + kc * 64 + kq * 4;
                v[it] = __ldcg((const float4*)(hprev + b * HIDDEN + kglob));
            }
            __syncthreads();
#pragma unroll
            for (int it = 0; it < 8; it++) {
                int q  = tid + it * 256;
                int g  = q >> 10;
                int b  = (q & 1023) >> 4;
                int kq = q & 15;
                float* dp = hst + g * (64 * HST_STRIDE) + (kq * 4) * HST_STRIDE + b;
                dp[0]              = v[it].x;
                dp[HST_STRIDE]     = v[it].y;
                dp[2 * HST_STRIDE] = v[it].z;
                dp[3 * HST_STRIDE] = v[it].w;
            }
            __syncthreads();

            const float* hs    = hst + gh * (64 * HST_STRIDE) + tm * 4;
            const float* wbase = Wt + (gh * 512 + kc * 64) * WT_STRIDE + tn * 4;
#pragma unroll 8
            for (int kk = 0; kk < 64; kk++) {
                float4 h4 = *(const float4*)(hs + kk * HST_STRIDE);
                float4 w4 = *(const float4*)(wbase + kk * WT_STRIDE);
                float ha[4] = {h4.x, h4.y, h4.z, h4.w};
                float wa[4] = {w4.x, w4.y, w4.z, w4.w};
#pragma unroll
                for (int i = 0; i < 4; i++)
#pragma unroll
                    for (int j = 0; j < 4; j++) acc[i][j] += ha[i] * wa[j];
            }
        }

        // Reduce K halves: group 1 -> smem, group 0 adds + builds gates
        __syncthreads();
        if (gh == 1) {
            float* rp = red + r * 16;
#pragma unroll
            for (int i = 0; i < 4; i++)
#pragma unroll
                for (int j = 0; j < 4; j++) rp[i * 4 + j] = acc[i][j];
        }
        __syncthreads();
        if (gh == 0) {
            const float* rp = red + r * 16;
#pragma unroll
            for (int i = 0; i < 4; i++) {
                int b = tm * 4 + i;
                float gx[4] = {xr[i].x, xr[i].y, xr[i].z, xr[i].w};
#pragma unroll
                for (int j = 0; j < 4; j++) {
                    gsm[b * 32 + tn * 4 + j] = acc[i][j] + rp[i * 4 + j] + gx[j];
                }
            }
        }
        __syncthreads();

        // Elementwise gates (reference order: i, f, o, g)
        {
            int pidx = tid * 2;
#pragma unroll
            for (int e = 0; e < 2; e++, pidx++) {
                int b  = pidx >> 3;
                int jl = pidx & 7;
                float gi = gsm[b * 32 + jl];
                float gf = gsm[b * 32 + 8 + jl];
                float go = gsm[b * 32 + 16 + jl];
                float gg = gsm[b * 32 + 24 + jl];
                float ig = 1.0f / (1.0f + expf(-gi));
                float fg = 1.0f / (1.0f + expf(-gf));
                float og = 1.0f / (1.0f + expf(-go));
                float cg = tanhf(gg);
                float c  = fg * csm[b * 8 + jl] + ig * cg;
                float h  = og * tanhf(c);
                csm[b * 8 + jl] = c;
                int col = cta * 8 + jl;
                __stcg(hnext + b * HIDDEN + col, h);
                if (t == SRCLEN - 1) {
                    out[b * HIDDEN + col] = h;
                    out[BATCH * HIDDEN + b * HIDDEN + col] = c;
                }
            }
        }

        // Grid barrier (monotonic per-step counters; release via L2)
        __threadfence();
        __syncthreads();
        if (tid == 0) {
            atomicAdd(&d_bar[t], 1u);
            while (*((volatile unsigned*)&d_bar[t]) < (unsigned)NCTA) { }
        }
        __syncthreads();
    }
}

// ---------------------------------------------------------------------------
extern "C" void kernel_launch(void* const* d_in, const int* in_sizes, int n_in,
                              void* d_out, int out_size)
{
    const int*   src = (const int*)d_in[0];
    const float* emb = (const float*)d_in[1];
    const float* Wx  = (const float*)d_in[2];
    const float* bx  = (const float*)d_in[3];
    const float* Wh  = (const float*)d_in[4];
    float*       out = (float*)d_out;

    init_kernel<<<257, 256>>>();
    xproj_kernel<<<dim3(G4 / 128, (SRCLEN * BATCH) / 128), 256>>>(src, emb, Wx, bx);

    size_t smem_bytes = (size_t)(36864 + 8704 + 512) * sizeof(float); // 184320 B
    cudaFuncSetAttribute(lstm_kernel, cudaFuncAttributeMaxDynamicSharedMemorySize,
                         (int)smem_bytes);
    lstm_kernel<<<NCTA, 256, smem_bytes>>>(Wh, out);
}

// round 4
// speedup vs baseline: 2.1752x; 2.1723x over previous
#include <cuda_runtime.h>
#include <math.h>
#include <stdint.h>

// Problem constants
#define VOCAB   32000
#define EMBED   512
#define HIDDEN  1024
#define G4      4096
#define BATCH   64
#define SRCLEN  1024
#define NCTA    128

// Scratch (device globals: allocation-free rule)
__device__ float    d_xproj[(size_t)SRCLEN * BATCH * G4];  // (t, b, g) fp32
// h in mma-fragment-native layout: idx = kt*512 + row*8 + c4*2 + ch
//   element (row=b, k) lives at kt=k>>3, c4=k&3, ch=(k>>2)&1
__device__ float    d_hf[2][NCTA * BATCH * 8];
__device__ unsigned d_bar[SRCLEN];

// ---------------------------------------------------------------------------
// helpers
// ---------------------------------------------------------------------------
__device__ __forceinline__ uint32_t f2tf32(float x) {
    uint32_t r;
    asm("cvt.rna.tf32.f32 %0, %1;" : "=r"(r) : "f"(x));
    return r;
}
__device__ __forceinline__ void mma8(float* c, const uint32_t* a, const uint32_t* b) {
    asm volatile(
        "mma.sync.aligned.m16n8k8.row.col.f32.tf32.tf32.f32 "
        "{%0,%1,%2,%3}, {%4,%5,%6,%7}, {%8,%9}, {%0,%1,%2,%3};"
        : "+f"(c[0]), "+f"(c[1]), "+f"(c[2]), "+f"(c[3])
        : "r"(a[0]), "r"(a[1]), "r"(a[2]), "r"(a[3]), "r"(b[0]), "r"(b[1]));
}
__device__ __forceinline__ float sigm(float x) {
    return 1.0f / (1.0f + __expf(-x));
}
__device__ __forceinline__ float tanhfast(float x) {
    return 2.0f / (1.0f + __expf(-2.0f * x)) - 1.0f;
}

// ---------------------------------------------------------------------------
__global__ void init_kernel() {
    int i = blockIdx.x * blockDim.x + threadIdx.x;
    if (i < NCTA * BATCH * 8) d_hf[0][i] = 0.0f;
    if (i < SRCLEN)           d_bar[i]  = 0u;
}

// ---------------------------------------------------------------------------
// x_proj via mma.sync tf32: C[m=65536][n=4096] = emb[src] @ Wx^T + bx
// CTA tile 128x128, K=512 in 16 chunks of 32, double-buffered smem.
// 8 warps, warp tile 64x32 (grid 2M x 4N). Swizzle: col' = (k + 4*(row&7))&31.
// ---------------------------------------------------------------------------
__global__ void __launch_bounds__(256, 1) xproj_kernel(
    const int* __restrict__ src, const float* __restrict__ emb,
    const float* __restrict__ Wx, const float* __restrict__ bx)
{
    extern __shared__ uint32_t xpsm[];
    uint32_t* As = xpsm;           // 2 * 128*32
    uint32_t* Bs = xpsm + 8192;    // 2 * 128*32
    __shared__ int tok[128];

    const int tid  = threadIdx.x;
    const int lane = tid & 31;
    const int warp = tid >> 5;
    const int wm   = warp & 1;
    const int wn   = warp >> 1;
    const int g    = lane >> 2;    // group id 0..7
    const int tg   = lane & 3;     // thread-in-group
    const int bm0  = blockIdx.y * 128;
    const int bn0  = blockIdx.x * 128;

    if (tid < 128) {
        int m = bm0 + tid;
        tok[tid] = src[(m & 63) * SRCLEN + (m >> 6)];
    }
    __syncthreads();

    float acc[4][4][4];
#pragma unroll
    for (int mt = 0; mt < 4; mt++)
#pragma unroll
        for (int nt = 0; nt < 4; nt++)
#pragma unroll
            for (int r = 0; r < 4; r++) acc[mt][nt][r] = 0.0f;

    const int sr  = tid >> 3;      // staging row 0..31 (of 128 via 4 iters)
    const int sf4 = tid & 7;       // float4 index in 32-wide chunk

    // stage chunk 0
#pragma unroll
    for (int it = 0; it < 4; it++) {
        int r = sr + it * 32;
        float4 va = __ldg((const float4*)(emb + (size_t)tok[r] * EMBED + sf4 * 4));
        float4 vb = __ldg((const float4*)(Wx  + (size_t)(bn0 + r) * EMBED + sf4 * 4));
        int c = (sf4 * 4 + 4 * (r & 7)) & 31;
        *(uint4*)&As[r * 32 + c] = make_uint4(f2tf32(va.x), f2tf32(va.y),
                                              f2tf32(va.z), f2tf32(va.w));
        *(uint4*)&Bs[r * 32 + c] = make_uint4(f2tf32(vb.x), f2tf32(vb.y),
                                              f2tf32(vb.z), f2tf32(vb.w));
    }
    __syncthreads();

    float4 pa[4], pb[4];
    for (int kc = 0; kc < 16; kc++) {
        const int buf = kc & 1;
        if (kc + 1 < 16) {
#pragma unroll
            for (int it = 0; it < 4; it++) {
                int r = sr + it * 32;
                pa[it] = __ldg((const float4*)(emb + (size_t)tok[r] * EMBED
                                               + (kc + 1) * 32 + sf4 * 4));
                pb[it] = __ldg((const float4*)(Wx + (size_t)(bn0 + r) * EMBED
                                               + (kc + 1) * 32 + sf4 * 4));
            }
        }
        const uint32_t* Ab = As + buf * 4096;
        const uint32_t* Bb = Bs + buf * 4096;
#pragma unroll
        for (int kt = 0; kt < 4; kt++) {
            const int kk = kt * 8 + tg;
            const int sw = 4 * g;
            uint32_t af[4][4], bf[4][2];
#pragma unroll
            for (int mt = 0; mt < 4; mt++) {
                int r0 = wm * 64 + mt * 16 + g;
                af[mt][0] = Ab[r0 * 32 + ((kk + sw) & 31)];
                af[mt][1] = Ab[(r0 + 8) * 32 + ((kk + sw) & 31)];
                af[mt][2] = Ab[r0 * 32 + ((kk + 4 + sw) & 31)];
                af[mt][3] = Ab[(r0 + 8) * 32 + ((kk + 4 + sw) & 31)];
            }
#pragma unroll
            for (int nt = 0; nt < 4; nt++) {
                int n0 = wn * 32 + nt * 8 + g;
                bf[nt][0] = Bb[n0 * 32 + ((kk + sw) & 31)];
                bf[nt][1] = Bb[n0 * 32 + ((kk + 4 + sw) & 31)];
            }
#pragma unroll
            for (int mt = 0; mt < 4; mt++)
#pragma unroll
                for (int nt = 0; nt < 4; nt++)
                    mma8(acc[mt][nt], af[mt], bf[nt]);
        }
        __syncthreads();
        if (kc + 1 < 16) {
            uint32_t* Ad = As + (buf ^ 1) * 4096;
            uint32_t* Bd = Bs + (buf ^ 1) * 4096;
#pragma unroll
            for (int it = 0; it < 4; it++) {
                int r = sr + it * 32;
                int c = (sf4 * 4 + 4 * (r & 7)) & 31;
                *(uint4*)&Ad[r * 32 + c] = make_uint4(f2tf32(pa[it].x), f2tf32(pa[it].y),
                                                      f2tf32(pa[it].z), f2tf32(pa[it].w));
                *(uint4*)&Bd[r * 32 + c] = make_uint4(f2tf32(pb[it].x), f2tf32(pb[it].y),
                                                      f2tf32(pb[it].z), f2tf32(pb[it].w));
            }
            __syncthreads();
        }
    }

    // epilogue: + bias, write fp32
#pragma unroll
    for (int nt = 0; nt < 4; nt++) {
        int col = bn0 + wn * 32 + nt * 8 + tg * 2;
        float b0 = __ldg(bx + col);
        float b1 = __ldg(bx + col + 1);
#pragma unroll
        for (int mt = 0; mt < 4; mt++)
#pragma unroll
            for (int rr = 0; rr < 2; rr++) {
                int m = bm0 + wm * 64 + mt * 16 + rr * 8 + g;
                float2 v = make_float2(acc[mt][nt][rr * 2] + b0,
                                       acc[mt][nt][rr * 2 + 1] + b1);
                *(float2*)(d_xproj + (size_t)m * G4 + col) = v;
            }
    }
}

// ---------------------------------------------------------------------------
// Recurrence via mma.sync tf32. 128 persistent CTAs x 128 threads (4 warps).
// Warp grid: wm = warp&1 (rows wm*32..+31), kh = warp>>1 (K half).
// Wh slice (32 gate cols x 1024 K) as tf32 in smem, swizzled:
//   word = kt*256 + n*8 + ((k&7 + n)&7)
// h read straight from gmem fragment layout with __ldcg (L2-coherent).
// Split-K reduced through psm; epilogue + h writeback on warps 0,1.
// ---------------------------------------------------------------------------
#define LSTM_SMEM_WORDS (32768 + 2112 + 2112)

__global__ void __launch_bounds__(128, 1) lstm_kernel(
    const float* __restrict__ Wh, float* __restrict__ out)
{
    extern __shared__ float lsm[];
    uint32_t* Bs  = (uint32_t*)lsm;          // 32768 words (128 KB)
    float*    psm = lsm + 32768;             // 64 x 33
    float*    xsm = lsm + 32768 + 2112;      // 64 x 33

    const int tid  = threadIdx.x;
    const int lane = tid & 31;
    const int warp = tid >> 5;
    const int cta  = blockIdx.x;
    const int wm   = warp & 1;
    const int kh   = warp >> 1;
    const int g    = lane >> 2;
    const int tg   = lane & 3;

    // One-time: Wh slice -> tf32 swizzled smem (coalesced: k fast-varying)
    for (int i = tid; i < 32 * HIDDEN; i += 128) {
        int lc = i >> 10;            // gate col 0..31
        int k  = i & 1023;
        int grow = (lc >> 3) * HIDDEN + cta * 8 + (lc & 7);
        float w = __ldg(Wh + (size_t)grow * HIDDEN + k);
        Bs[(k >> 3) * 256 + lc * 8 + (((k & 7) + lc) & 7)] = f2tf32(w);
    }
    __syncthreads();

    // B fragment word offsets (within a kt block of 256 words)
    int bo0[4], bo1[4];
#pragma unroll
    for (int nt = 0; nt < 4; nt++) {
        int n = nt * 8 + g;
        bo0[nt] = n * 8 + ((tg + n) & 7);
        bo1[nt] = n * 8 + ((tg + 4 + n) & 7);
    }

    float cst[8];
#pragma unroll
    for (int i = 0; i < 8; i++) cst[i] = 0.0f;

    for (int t = 0; t < SRCLEN; t++) {
        // prefetch xproj slice into xsm[b][lc] (all 128 threads)
#pragma unroll
        for (int e = 0; e < 2; e++) {
            int p = tid * 2 + e;          // 0..255 = (b, gate)
            int b = p >> 2, gg = p & 3;
            const float* xp = d_xproj + ((size_t)t * BATCH + b) * G4
                              + gg * HIDDEN + cta * 8;
            float4 v0 = __ldg((const float4*)xp);
            float4 v1 = __ldg((const float4*)(xp + 4));
            float* dst = xsm + b * 33 + gg * 8;
            dst[0] = v0.x; dst[1] = v0.y; dst[2] = v0.z; dst[3] = v0.w;
            dst[4] = v1.x; dst[5] = v1.y; dst[6] = v1.z; dst[7] = v1.w;
        }

        float acc[2][4][4];
#pragma unroll
        for (int mt = 0; mt < 2; mt++)
#pragma unroll
            for (int nt = 0; nt < 4; nt++)
#pragma unroll
                for (int r = 0; r < 4; r++) acc[mt][nt][r] = 0.0f;

        // A base: fragment float2 at kt*512 + row*8 + tg*2
        const float* a00 = d_hf[t & 1] + (size_t)(kh * 64) * 512
                           + (wm * 32 + g) * 8 + tg * 2;
        const uint32_t* bb = Bs + (kh * 64) * 256;

#pragma unroll 4
        for (int kt = 0; kt < 64; kt++) {
            const float* ap = a00 + kt * 512;
            uint32_t a[2][4];
            float2 q;
            q = __ldcg((const float2*)(ap));        a[0][0] = __float_as_uint(q.x); a[0][2] = __float_as_uint(q.y);
            q = __ldcg((const float2*)(ap + 64));   a[0][1] = __float_as_uint(q.x); a[0][3] = __float_as_uint(q.y);
            q = __ldcg((const float2*)(ap + 128));  a[1][0] = __float_as_uint(q.x); a[1][2] = __float_as_uint(q.y);
            q = __ldcg((const float2*)(ap + 192));  a[1][1] = __float_as_uint(q.x); a[1][3] = __float_as_uint(q.y);
            const uint32_t* bp = bb + kt * 256;
            uint32_t bf[4][2];
#pragma unroll
            for (int nt = 0; nt < 4; nt++) {
                bf[nt][0] = bp[bo0[nt]];
                bf[nt][1] = bp[bo1[nt]];
            }
#pragma unroll
            for (int mt = 0; mt < 2; mt++)
#pragma unroll
                for (int nt = 0; nt < 4; nt++)
                    mma8(acc[mt][nt], a[mt], bf[nt]);
        }

        // split-K reduce: kh=1 warps publish partials
        if (kh == 1) {
#pragma unroll
            for (int mt = 0; mt < 2; mt++)
#pragma unroll
                for (int nt = 0; nt < 4; nt++)
#pragma unroll
                    for (int r = 0; r < 4; r++) {
                        int row = wm * 32 + mt * 16 + (r >> 1) * 8 + g;
                        int col = nt * 8 + tg * 2 + (r & 1);
                        psm[row * 33 + col] = acc[mt][nt][r];
                    }
        }
        __syncthreads();

        if (kh == 0) {
#pragma unroll
            for (int mt = 0; mt < 2; mt++)
#pragma unroll
                for (int nt = 0; nt < 4; nt++)
#pragma unroll
                    for (int r = 0; r < 4; r++) {
                        int row = wm * 32 + mt * 16 + (r >> 1) * 8 + g;
                        int col = nt * 8 + tg * 2 + (r & 1);
                        acc[mt][nt][r] += psm[row * 33 + col];
                    }

            float* hout = d_hf[(t + 1) & 1] + cta * 512;
#pragma unroll
            for (int mt = 0; mt < 2; mt++)
#pragma unroll
                for (int rr = 0; rr < 2; rr++)
#pragma unroll
                    for (int jo = 0; jo < 2; jo++) {
                        int b  = wm * 32 + mt * 16 + rr * 8 + g;
                        int jj = tg * 2 + jo;
                        int r  = rr * 2 + jo;
                        float gi = acc[mt][0][r] + xsm[b * 33 + jj];
                        float gf = acc[mt][1][r] + xsm[b * 33 + 8 + jj];
                        float go = acc[mt][2][r] + xsm[b * 33 + 16 + jj];
                        float gv = acc[mt][3][r] + xsm[b * 33 + 24 + jj];
                        float ig = sigm(gi), fg = sigm(gf), og = sigm(go);
                        float cg = tanhfast(gv);
                        int ci   = mt * 4 + rr * 2 + jo;
                        float c  = fg * cst[ci] + ig * cg;
                        cst[ci]  = c;
                        float h  = og * tanhfast(c);
                        hout[b * 8 + (jj & 3) * 2 + (jj >> 2)] =
                            __uint_as_float(f2tf32(h));
                        if (t == SRCLEN - 1) {
                            out[b * HIDDEN + cta * 8 + jj] = h;
                            out[BATCH * HIDDEN + b * HIDDEN + cta * 8 + jj] = c;
                        }
                    }
        }

        // grid barrier (monotonic per-step counters)
        __threadfence();
        __syncthreads();
        if (tid == 0) {
            atomicAdd(&d_bar[t], 1u);
            while (*((volatile unsigned*)&d_bar[t]) < (unsigned)NCTA) { }
        }
        __syncthreads();
    }
}

// ---------------------------------------------------------------------------
extern "C" void kernel_launch(void* const* d_in, const int* in_sizes, int n_in,
                              void* d_out, int out_size)
{
    const int*   src = (const int*)d_in[0];
    const float* emb = (const float*)d_in[1];
    const float* Wx  = (const float*)d_in[2];
    const float* bx  = (const float*)d_in[3];
    const float* Wh  = (const float*)d_in[4];
    float*       out = (float*)d_out;

    init_kernel<<<(NCTA * BATCH * 8 + 255) / 256, 256>>>();

    cudaFuncSetAttribute(xproj_kernel, cudaFuncAttributeMaxDynamicSharedMemorySize,
                         16384 * 4);
    xproj_kernel<<<dim3(G4 / 128, (SRCLEN * BATCH) / 128), 256, 16384 * 4>>>(
        src, emb, Wx, bx);

    cudaFuncSetAttribute(lstm_kernel, cudaFuncAttributeMaxDynamicSharedMemorySize,
                         LSTM_SMEM_WORDS * 4);
    lstm_kernel<<<NCTA, 128, LSTM_SMEM_WORDS * 4>>>(Wh, out);
}

// round 5
// speedup vs baseline: 3.7773x; 1.7365x over previous
#include <cuda_runtime.h>
#include <cuda_fp16.h>
#include <math.h>
#include <stdint.h>

#define VOCAB   32000
#define EMBED   512
#define HIDDEN  1024
#define G4      4096
#define BATCH   64
#define SRCLEN  1024
#define NCTA    128

// Scratch (device globals)
__device__ float    d_xproj[(size_t)SRCLEN * BATCH * G4];   // (t,b,g) fp32
// h as half2 words in mma-A-fragment layout:
//   word(kt, row, tg, j) = kt*512 + row*8 + tg*2 + j
//   word holds halves (k = kt*16 + 2tg + j*8, +1)
__device__ unsigned d_hf[2][64 * 512];
__device__ unsigned d_bar[SRCLEN];

// ---------------------------------------------------------------------------
__device__ __forceinline__ void mma16(float* c, const uint32_t* a, const uint32_t* b) {
    asm volatile(
        "mma.sync.aligned.m16n8k16.row.col.f32.f16.f16.f32 "
        "{%0,%1,%2,%3}, {%4,%5,%6,%7}, {%8,%9}, {%0,%1,%2,%3};"
        : "+f"(c[0]), "+f"(c[1]), "+f"(c[2]), "+f"(c[3])
        : "r"(a[0]), "r"(a[1]), "r"(a[2]), "r"(a[3]), "r"(b[0]), "r"(b[1]));
}
__device__ __forceinline__ uint32_t h2u(float x, float y) {
    __half2 h = __floats2half2_rn(x, y);
    return *(uint32_t*)&h;
}
__device__ __forceinline__ float sigm(float x) { return 1.0f / (1.0f + __expf(-x)); }
__device__ __forceinline__ float tanhfast(float x) {
    return 2.0f / (1.0f + __expf(-2.0f * x)) - 1.0f;
}

// ---------------------------------------------------------------------------
__global__ void init_kernel() {
    int i = blockIdx.x * blockDim.x + threadIdx.x;
    if (i < 64 * 512) d_hf[0][i] = 0u;
    if (i < SRCLEN)   d_bar[i]  = 0u;
}

// ---------------------------------------------------------------------------
// x_proj (fp16 mma): C[65536,4096] = emb[src] @ Wx^T + bx
// CTA 128x128, K=512 in 16 chunks of 32, double-buffered fragment-native smem.
// 8 warps: wm=warp&1 (64 rows), wn=warp>>1 (32 cols); warp tile 64x32.
// smem word layout per chunk: kto*XP_KW + row*8 + tg*2 + j (kto = K16 tile).
// ---------------------------------------------------------------------------
#define XP_KW   1040                    // kto stride (words), bank-shifted
#define XP_BUF  (2 * XP_KW)             // words per matrix per buffer

__global__ void __launch_bounds__(256, 1) xproj_kernel(
    const int* __restrict__ src, const float* __restrict__ emb,
    const float* __restrict__ Wx, const float* __restrict__ bx)
{
    extern __shared__ uint32_t xpsm[];          // 4*XP_BUF words
    uint32_t* As = xpsm;                        // [2][XP_BUF]
    uint32_t* Bs = xpsm + 2 * XP_BUF;
    __shared__ int tok[128];

    const int tid  = threadIdx.x;
    const int lane = tid & 31;
    const int warp = tid >> 5;
    const int wm   = warp & 1;
    const int wn   = warp >> 1;
    const int g    = lane >> 2;
    const int tg   = lane & 3;
    const int bm0  = blockIdx.y * 128;
    const int bn0  = blockIdx.x * 128;

    if (tid < 128) {
        int m = bm0 + tid;
        tok[tid] = src[(m & 63) * SRCLEN + (m >> 6)];
    }
    __syncthreads();

    float acc[4][4][4];
#pragma unroll
    for (int mt = 0; mt < 4; mt++)
#pragma unroll
        for (int nt = 0; nt < 4; nt++)
#pragma unroll
            for (int r = 0; r < 4; r++) acc[mt][nt][r] = 0.0f;

    const int sr  = tid >> 3;         // staging row (x4 iters)
    const int sf4 = tid & 7;          // float4 idx within 32-k chunk
    const int kto = sf4 >> 2;
    const int rem = sf4 & 3;
    const int so  = ((rem & 1) << 2) | (rem >> 1);

    // stage chunk 0
#pragma unroll
    for (int it = 0; it < 4; it++) {
        int r = sr + it * 32;
        float4 va = __ldg((const float4*)(emb + (size_t)tok[r] * EMBED + sf4 * 4));
        float4 vb = __ldg((const float4*)(Wx  + (size_t)(bn0 + r) * EMBED + sf4 * 4));
        int base = kto * XP_KW + r * 8;
        As[base + so]     = h2u(va.x, va.y);
        As[base + so + 2] = h2u(va.z, va.w);
        Bs[base + so]     = h2u(vb.x, vb.y);
        Bs[base + so + 2] = h2u(vb.z, vb.w);
    }
    __syncthreads();

    float4 pa[4], pb[4];
    for (int kc = 0; kc < 16; kc++) {
        const int buf = kc & 1;
        if (kc + 1 < 16) {
#pragma unroll
            for (int it = 0; it < 4; it++) {
                int r = sr + it * 32;
                pa[it] = __ldg((const float4*)(emb + (size_t)tok[r] * EMBED
                                               + (kc + 1) * 32 + sf4 * 4));
                pb[it] = __ldg((const float4*)(Wx + (size_t)(bn0 + r) * EMBED
                                               + (kc + 1) * 32 + sf4 * 4));
            }
        }
        const uint32_t* Ab = As + buf * XP_BUF;
        const uint32_t* Bb = Bs + buf * XP_BUF;
#pragma unroll
        for (int kt = 0; kt < 2; kt++) {
            const int kb = kt * XP_KW;
            uint32_t af[4][4], bf[4][2];
#pragma unroll
            for (int mt = 0; mt < 4; mt++) {
                int r0 = wm * 64 + mt * 16 + g;
                uint2 u0 = *(const uint2*)&Ab[kb + r0 * 8 + tg * 2];
                uint2 u1 = *(const uint2*)&Ab[kb + (r0 + 8) * 8 + tg * 2];
                af[mt][0] = u0.x; af[mt][2] = u0.y;
                af[mt][1] = u1.x; af[mt][3] = u1.y;
            }
#pragma unroll
            for (int nt = 0; nt < 4; nt++) {
                int n0 = wn * 32 + nt * 8 + g;
                uint2 u = *(const uint2*)&Bb[kb + n0 * 8 + tg * 2];
                bf[nt][0] = u.x; bf[nt][1] = u.y;
            }
#pragma unroll
            for (int mt = 0; mt < 4; mt++)
#pragma unroll
                for (int nt = 0; nt < 4; nt++)
                    mma16(acc[mt][nt], af[mt], bf[nt]);
        }
        __syncthreads();
        if (kc + 1 < 16) {
            uint32_t* Ad = As + (buf ^ 1) * XP_BUF;
            uint32_t* Bd = Bs + (buf ^ 1) * XP_BUF;
#pragma unroll
            for (int it = 0; it < 4; it++) {
                int r = sr + it * 32;
                int base = kto * XP_KW + r * 8;
                Ad[base + so]     = h2u(pa[it].x, pa[it].y);
                Ad[base + so + 2] = h2u(pa[it].z, pa[it].w);
                Bd[base + so]     = h2u(pb[it].x, pb[it].y);
                Bd[base + so + 2] = h2u(pb[it].z, pb[it].w);
            }
            __syncthreads();
        }
    }

    // epilogue: + bias, fp32 out
#pragma unroll
    for (int nt = 0; nt < 4; nt++) {
        int col = bn0 + wn * 32 + nt * 8 + tg * 2;
        float b0 = __ldg(bx + col);
        float b1 = __ldg(bx + col + 1);
#pragma unroll
        for (int mt = 0; mt < 4; mt++)
#pragma unroll
            for (int rr = 0; rr < 2; rr++) {
                int m = bm0 + wm * 64 + mt * 16 + rr * 8 + g;
                float2 v = make_float2(acc[mt][nt][rr * 2] + b0,
                                       acc[mt][nt][rr * 2 + 1] + b1);
                *(float2*)(d_xproj + (size_t)m * G4 + col) = v;
            }
    }
}

// ---------------------------------------------------------------------------
// Recurrence (fp16 mma): 128 persistent CTAs x 256 threads (8 warps).
// wm = warp&1 -> rows wm*32..+31 ; kh = warp>>1 -> K quarter (16 kt of K16).
// Wh slice (32 cols x 1024 K) fp16 in smem, B-fragment layout:
//   word = kt*256 + n*8 + tg*2 + j  (LDS.64 -> (b0,b1), conflict-free)
// h read from gmem fragment words with __ldcg; 4-way split-K via psm.
// ---------------------------------------------------------------------------
#define PSM_STRIDE 40
#define LSTM_SMEM_WORDS (16384 + 3 * 64 * PSM_STRIDE + 64 * 33)   // 26176

__global__ void __launch_bounds__(256, 1) lstm_kernel(
    const float* __restrict__ Wh, float* __restrict__ out)
{
    extern __shared__ float lsm[];
    uint32_t* Bs  = (uint32_t*)lsm;                 // 16384 words (64 KB)
    float*    psm = lsm + 16384;                    // [3][64][40]
    float*    xsm = lsm + 16384 + 3 * 64 * PSM_STRIDE;  // [64][33]

    const int tid  = threadIdx.x;
    const int lane = tid & 31;
    const int warp = tid >> 5;
    const int cta  = blockIdx.x;
    const int wm   = warp & 1;
    const int kh   = warp >> 1;         // 0..3
    const int g    = lane >> 2;
    const int tg   = lane & 3;

    // One-time: Wh slice -> fp16 B-fragment smem (k fast -> coalesced LDG)
    for (int i = tid; i < 32 * HIDDEN; i += 256) {
        int lc = i >> 10;               // gate col 0..31
        int k  = i & 1023;
        int grow = (lc >> 3) * HIDDEN + cta * 8 + (lc & 7);
        float w = __ldg(Wh + (size_t)grow * HIDDEN + k);
        int kl = k & 15;
        int word = (k >> 4) * 256 + lc * 8 + ((kl & 7) >> 1) * 2 + (kl >> 3);
        ((__half*)Bs)[word * 2 + (k & 1)] = __float2half_rn(w);
    }
    __syncthreads();

    const int xb = tid >> 2;            // batch row for xproj prefetch
    const int xg = tid & 3;             // gate

    float cst[8];
#pragma unroll
    for (int i = 0; i < 8; i++) cst[i] = 0.0f;

    const int aoff = (wm * 32 + g) * 8 + tg * 2;

    for (int t = 0; t < SRCLEN; t++) {
        // xproj gates -> registers (store to smem only at reduce sync)
        const float* xp = d_xproj + ((size_t)t * BATCH + xb) * G4
                          + xg * HIDDEN + cta * 8;
        float4 xr0 = __ldg((const float4*)xp);
        float4 xr1 = __ldg((const float4*)(xp + 4));

        float acc[2][4][4];
#pragma unroll
        for (int mt = 0; mt < 2; mt++)
#pragma unroll
            for (int nt = 0; nt < 4; nt++)
#pragma unroll
                for (int r = 0; r < 4; r++) acc[mt][nt][r] = 0.0f;

        const unsigned* hb = d_hf[t & 1];

#pragma unroll 4
        for (int ki = 0; ki < 16; ki++) {
            const int kt = kh * 16 + ki;
            const int kb = kt * 512;
            uint2 u00 = __ldcg((const uint2*)&hb[kb + aoff]);          // mt0, row g
            uint2 u01 = __ldcg((const uint2*)&hb[kb + aoff + 64]);     // mt0, row g+8
            uint2 u10 = __ldcg((const uint2*)&hb[kb + aoff + 128]);    // mt1, row g
            uint2 u11 = __ldcg((const uint2*)&hb[kb + aoff + 192]);    // mt1, row g+8
            uint32_t a0[4] = {u00.x, u01.x, u00.y, u01.y};
            uint32_t a1[4] = {u10.x, u11.x, u10.y, u11.y};
            const uint32_t* bp = Bs + kt * 256;
            uint32_t bf[4][2];
#pragma unroll
            for (int nt = 0; nt < 4; nt++) {
                uint2 u = *(const uint2*)&bp[(nt * 8 + g) * 8 + tg * 2];
                bf[nt][0] = u.x; bf[nt][1] = u.y;
            }
#pragma unroll
            for (int nt = 0; nt < 4; nt++) {
                mma16(acc[0][nt], a0, bf[nt]);
                mma16(acc[1][nt], a1, bf[nt]);
            }
        }

        // publish split-K partials (kh 1..3)
        if (kh != 0) {
            float* pp = psm + (kh - 1) * (64 * PSM_STRIDE);
#pragma unroll
            for (int mt = 0; mt < 2; mt++)
#pragma unroll
                for (int rr = 0; rr < 2; rr++) {
                    int row = wm * 32 + mt * 16 + rr * 8 + g;
#pragma unroll
                    for (int nt = 0; nt < 4; nt++)
                        *(float2*)&pp[row * PSM_STRIDE + nt * 8 + tg * 2] =
                            make_float2(acc[mt][nt][rr * 2], acc[mt][nt][rr * 2 + 1]);
                }
        }
        // xproj regs -> smem
        {
            float* dst = xsm + xb * 33 + xg * 8;
            dst[0] = xr0.x; dst[1] = xr0.y; dst[2] = xr0.z; dst[3] = xr0.w;
            dst[4] = xr1.x; dst[5] = xr1.y; dst[6] = xr1.z; dst[7] = xr1.w;
        }
        __syncthreads();

        if (kh == 0) {
            unsigned* hn = d_hf[(t + 1) & 1];
#pragma unroll
            for (int mt = 0; mt < 2; mt++)
#pragma unroll
                for (int rr = 0; rr < 2; rr++) {
                    int b = wm * 32 + mt * 16 + rr * 8 + g;
                    float gv[4][2];
#pragma unroll
                    for (int nt = 0; nt < 4; nt++) {
                        float2 s = make_float2(acc[mt][nt][rr * 2],
                                               acc[mt][nt][rr * 2 + 1]);
#pragma unroll
                        for (int p = 0; p < 3; p++) {
                            float2 q = *(const float2*)&psm[p * (64 * PSM_STRIDE)
                                        + b * PSM_STRIDE + nt * 8 + tg * 2];
                            s.x += q.x; s.y += q.y;
                        }
                        gv[nt][0] = s.x + xsm[b * 33 + nt * 8 + tg * 2];
                        gv[nt][1] = s.y + xsm[b * 33 + nt * 8 + tg * 2 + 1];
                    }
                    float h2v[2], c2v[2];
#pragma unroll
                    for (int jo = 0; jo < 2; jo++) {
                        float ig = sigm(gv[0][jo]);
                        float fg = sigm(gv[1][jo]);
                        float og = sigm(gv[2][jo]);
                        float cg = tanhfast(gv[3][jo]);
                        int ci   = mt * 4 + rr * 2 + jo;
                        float c  = fg * cst[ci] + ig * cg;
                        cst[ci]  = c;
                        h2v[jo]  = og * tanhfast(c);
                        c2v[jo]  = c;
                    }
                    int widx = (cta >> 1) * 512 + b * 8 + tg * 2 + (cta & 1);
                    __stcg(&hn[widx], h2u(h2v[0], h2v[1]));
                    if (t == SRCLEN - 1) {
                        int col = cta * 8 + tg * 2;
                        *(float2*)(out + b * HIDDEN + col) =
                            make_float2(h2v[0], h2v[1]);
                        *(float2*)(out + BATCH * HIDDEN + b * HIDDEN + col) =
                            make_float2(c2v[0], c2v[1]);
                    }
                }
        }

        // grid barrier (monotonic per-step counters)
        __threadfence();
        __syncthreads();
        if (tid == 0) {
            atomicAdd(&d_bar[t], 1u);
            while (*((volatile unsigned*)&d_bar[t]) < (unsigned)NCTA) { }
        }
        __syncthreads();
    }
}

// ---------------------------------------------------------------------------
extern "C" void kernel_launch(void* const* d_in, const int* in_sizes, int n_in,
                              void* d_out, int out_size)
{
    const int*   src = (const int*)d_in[0];
    const float* emb = (const float*)d_in[1];
    const float* Wx  = (const float*)d_in[2];
    const float* bx  = (const float*)d_in[3];
    const float* Wh  = (const float*)d_in[4];
    float*       out = (float*)d_out;

    init_kernel<<<128, 256>>>();

    cudaFuncSetAttribute(xproj_kernel, cudaFuncAttributeMaxDynamicSharedMemorySize,
                         4 * XP_BUF * 4);
    xproj_kernel<<<dim3(G4 / 128, (SRCLEN * BATCH) / 128), 256, 4 * XP_BUF * 4>>>(
        src, emb, Wx, bx);

    cudaFuncSetAttribute(lstm_kernel, cudaFuncAttributeMaxDynamicSharedMemorySize,
                         LSTM_SMEM_WORDS * 4);
    lstm_kernel<<<NCTA, 256, LSTM_SMEM_WORDS * 4>>>(Wh, out);
}

// round 7
// speedup vs baseline: 5.3541x; 1.4175x over previous
#include <cuda_runtime.h>
#include <cuda_fp16.h>
#include <math.h>
#include <stdint.h>

#define VOCAB   32000
#define EMBED   512
#define HIDDEN  1024
#define G4      4096
#define BATCH   64
#define SRCLEN  1024
#define NCTA    128

// Scratch (device globals)
__device__ float    d_xproj[(size_t)SRCLEN * BATCH * G4];   // (t,b,g) fp32
// h as half2 words in mma-A-fragment layout:
//   word(kt, row, tg, j) = kt*512 + row*8 + tg*2 + j ; halves k = kt*16+2tg+8j, +1
__device__ unsigned d_hf[2][64 * 512];
__device__ unsigned d_bar8[SRCLEN * 8];     // per-step spread arrival counters

// ---------------------------------------------------------------------------
__device__ __forceinline__ void mma16(float* c, const uint32_t* a, const uint32_t* b) {
    asm volatile(
        "mma.sync.aligned.m16n8k16.row.col.f32.f16.f16.f32 "
        "{%0,%1,%2,%3}, {%4,%5,%6,%7}, {%8,%9}, {%0,%1,%2,%3};"
        : "+f"(c[0]), "+f"(c[1]), "+f"(c[2]), "+f"(c[3])
        : "r"(a[0]), "r"(a[1]), "r"(a[2]), "r"(a[3]), "r"(b[0]), "r"(b[1]));
}
__device__ __forceinline__ uint32_t h2u(float x, float y) {
    __half2 h = __floats2half2_rn(x, y);
    return *(uint32_t*)&h;
}
__device__ __forceinline__ float tanh_mufu(float x) {
    float y;
    asm("tanh.approx.f32 %0, %1;" : "=f"(y) : "f"(x));
    return y;
}
__device__ __forceinline__ float sigm(float x) {          // 1 MUFU
    return fmaf(0.5f, tanh_mufu(0.5f * x), 0.5f);
}
__device__ __forceinline__ float tanh_precise(float x) {  // 2 MUFU (EX2+RCP)
    return 2.0f / (1.0f + __expf(-2.0f * x)) - 1.0f;
}
__device__ __forceinline__ unsigned ldflag(const unsigned* p) {
    unsigned v;
    asm volatile("ld.global.cg.u32 %0, [%1];" : "=r"(v) : "l"(p) : "memory");
    return v;
}

// ---------------------------------------------------------------------------
__global__ void init_kernel() {
    int i = blockIdx.x * blockDim.x + threadIdx.x;
    if (i < 64 * 512)   d_hf[0][i]  = 0u;
    if (i < SRCLEN * 8) d_bar8[i]   = 0u;
}

// ---------------------------------------------------------------------------
// x_proj (fp16 mma): C[65536,4096] = emb[src] @ Wx^T + bx   (unchanged R5)
// ---------------------------------------------------------------------------
#define XP_KW   1040
#define XP_BUF  (2 * XP_KW)

__global__ void __launch_bounds__(256, 1) xproj_kernel(
    const int* __restrict__ src, const float* __restrict__ emb,
    const float* __restrict__ Wx, const float* __restrict__ bx)
{
    extern __shared__ uint32_t xpsm[];
    uint32_t* As = xpsm;
    uint32_t* Bs = xpsm + 2 * XP_BUF;
    __shared__ int tok[128];

    const int tid  = threadIdx.x;
    const int lane = tid & 31;
    const int warp = tid >> 5;
    const int wm   = warp & 1;
    const int wn   = warp >> 1;
    const int g    = lane >> 2;
    const int tg   = lane & 3;
    const int bm0  = blockIdx.y * 128;
    const int bn0  = blockIdx.x * 128;

    if (tid < 128) {
        int m = bm0 + tid;
        tok[tid] = src[(m & 63) * SRCLEN + (m >> 6)];
    }
    __syncthreads();

    float acc[4][4][4];
#pragma unroll
    for (int mt = 0; mt < 4; mt++)
#pragma unroll
        for (int nt = 0; nt < 4; nt++)
#pragma unroll
            for (int r = 0; r < 4; r++) acc[mt][nt][r] = 0.0f;

    const int sr  = tid >> 3;
    const int sf4 = tid & 7;
    const int kto = sf4 >> 2;
    const int rem = sf4 & 3;
    const int so  = ((rem & 1) << 2) | (rem >> 1);

#pragma unroll
    for (int it = 0; it < 4; it++) {
        int r = sr + it * 32;
        float4 va = __ldg((const float4*)(emb + (size_t)tok[r] * EMBED + sf4 * 4));
        float4 vb = __ldg((const float4*)(Wx  + (size_t)(bn0 + r) * EMBED + sf4 * 4));
        int base = kto * XP_KW + r * 8;
        As[base + so]     = h2u(va.x, va.y);
        As[base + so + 2] = h2u(va.z, va.w);
        Bs[base + so]     = h2u(vb.x, vb.y);
        Bs[base + so + 2] = h2u(vb.z, vb.w);
    }
    __syncthreads();

    float4 pa[4], pb[4];
    for (int kc = 0; kc < 16; kc++) {
        const int buf = kc & 1;
        if (kc + 1 < 16) {
#pragma unroll
            for (int it = 0; it < 4; it++) {
                int r = sr + it * 32;
                pa[it] = __ldg((const float4*)(emb + (size_t)tok[r] * EMBED
                                               + (kc + 1) * 32 + sf4 * 4));
                pb[it] = __ldg((const float4*)(Wx + (size_t)(bn0 + r) * EMBED
                                               + (kc + 1) * 32 + sf4 * 4));
            }
        }
        const uint32_t* Ab = As + buf * XP_BUF;
        const uint32_t* Bb = Bs + buf * XP_BUF;
#pragma unroll
        for (int kt = 0; kt < 2; kt++) {
            const int kb = kt * XP_KW;
            uint32_t af[4][4], bf[4][2];
#pragma unroll
            for (int mt = 0; mt < 4; mt++) {
                int r0 = wm * 64 + mt * 16 + g;
                uint2 u0 = *(const uint2*)&Ab[kb + r0 * 8 + tg * 2];
                uint2 u1 = *(const uint2*)&Ab[kb + (r0 + 8) * 8 + tg * 2];
                af[mt][0] = u0.x; af[mt][2] = u0.y;
                af[mt][1] = u1.x; af[mt][3] = u1.y;
            }
#pragma unroll
            for (int nt = 0; nt < 4; nt++) {
                int n0 = wn * 32 + nt * 8 + g;
                uint2 u = *(const uint2*)&Bb[kb + n0 * 8 + tg * 2];
                bf[nt][0] = u.x; bf[nt][1] = u.y;
            }
#pragma unroll
            for (int mt = 0; mt < 4; mt++)
#pragma unroll
                for (int nt = 0; nt < 4; nt++)
                    mma16(acc[mt][nt], af[mt], bf[nt]);
        }
        __syncthreads();
        if (kc + 1 < 16) {
            uint32_t* Ad = As + (buf ^ 1) * XP_BUF;
            uint32_t* Bd = Bs + (buf ^ 1) * XP_BUF;
#pragma unroll
            for (int it = 0; it < 4; it++) {
                int r = sr + it * 32;
                int base = kto * XP_KW + r * 8;
                Ad[base + so]     = h2u(pa[it].x, pa[it].y);
                Ad[base + so + 2] = h2u(pa[it].z, pa[it].w);
                Bd[base + so]     = h2u(pb[it].x, pb[it].y);
                Bd[base + so + 2] = h2u(pb[it].z, pb[it].w);
            }
            __syncthreads();
        }
    }

#pragma unroll
    for (int nt = 0; nt < 4; nt++) {
        int col = bn0 + wn * 32 + nt * 8 + tg * 2;
        float b0 = __ldg(bx + col);
        float b1 = __ldg(bx + col + 1);
#pragma unroll
        for (int mt = 0; mt < 4; mt++)
#pragma unroll
            for (int rr = 0; rr < 2; rr++) {
                int m = bm0 + wm * 64 + mt * 16 + rr * 8 + g;
                float2 v = make_float2(acc[mt][nt][rr * 2] + b0,
                                       acc[mt][nt][rr * 2 + 1] + b1);
                *(float2*)(d_xproj + (size_t)m * G4 + col) = v;
            }
    }
}

// ---------------------------------------------------------------------------
// Recurrence (fp16 mma), R7: MUFU.TANH epilogue + 8-way-spread atomic barrier.
// 128 persistent CTAs x 256 threads. wm=warp&1 (rows), kh=warp>>1 (K quarter).
// psm[5][64][40]: partials kh=0..3 plus xproj gates as p=4.
// Epilogue: thread tid -> (b = tid>>2, col-pair u = tid&3), cst in registers.
// ---------------------------------------------------------------------------
#define PSTR 40
#define LSTM_SMEM_WORDS (16384 + 5 * 64 * PSTR)    // 29184 words = 116736 B

__global__ void __launch_bounds__(256, 1) lstm_kernel(
    const float* __restrict__ Wh, float* __restrict__ out)
{
    extern __shared__ float lsm[];
    uint32_t* Bs  = (uint32_t*)lsm;                 // 16384 words (64 KB)
    float*    psm = lsm + 16384;                    // [5][64][PSTR]

    const int tid  = threadIdx.x;
    const int lane = tid & 31;
    const int warp = tid >> 5;
    const int cta  = blockIdx.x;
    const int wm   = warp & 1;
    const int kh   = warp >> 1;
    const int g    = lane >> 2;
    const int tg   = lane & 3;

    // One-time: Wh slice -> fp16 B-fragment smem
    for (int i = tid; i < 32 * HIDDEN; i += 256) {
        int lc = i >> 10;
        int k  = i & 1023;
        int grow = (lc >> 3) * HIDDEN + cta * 8 + (lc & 7);
        float w = __ldg(Wh + (size_t)grow * HIDDEN + k);
        int kl = k & 15;
        int word = (k >> 4) * 256 + lc * 8 + ((kl & 7) >> 1) * 2 + (kl >> 3);
        ((__half*)Bs)[word * 2 + (k & 1)] = __float2half_rn(w);
    }
    __syncthreads();

    const int eb = tid >> 2;        // epilogue batch row
    const int eu = tid & 3;         // epilogue col-pair (j = 2eu, 2eu+1)
    float cst0 = 0.0f, cst1 = 0.0f;

    const int aoff  = (wm * 32 + g) * 8 + tg * 2;
    const int hword = (cta >> 1) * 512 + eb * 8 + eu * 2 + (cta & 1);

    for (int t = 0; t < SRCLEN; t++) {
        // xproj gates -> registers (gate eu, cols 0..7 of this CTA, row eb)
        const float* xp = d_xproj + ((size_t)t * BATCH + eb) * G4
                          + eu * HIDDEN + cta * 8;
        float4 xr0 = __ldg((const float4*)xp);
        float4 xr1 = __ldg((const float4*)(xp + 4));

        float acc[2][4][4];
#pragma unroll
        for (int mt = 0; mt < 2; mt++)
#pragma unroll
            for (int nt = 0; nt < 4; nt++)
#pragma unroll
                for (int r = 0; r < 4; r++) acc[mt][nt][r] = 0.0f;

        const unsigned* hb = d_hf[t & 1];

#pragma unroll 4
        for (int ki = 0; ki < 16; ki++) {
            const int kt = kh * 16 + ki;
            const int kb = kt * 512;
            uint2 u00 = __ldcg((const uint2*)&hb[kb + aoff]);
            uint2 u01 = __ldcg((const uint2*)&hb[kb + aoff + 64]);
            uint2 u10 = __ldcg((const uint2*)&hb[kb + aoff + 128]);
            uint2 u11 = __ldcg((const uint2*)&hb[kb + aoff + 192]);
            uint32_t a0[4] = {u00.x, u01.x, u00.y, u01.y};
            uint32_t a1[4] = {u10.x, u11.x, u10.y, u11.y};
            const uint32_t* bp = Bs + kt * 256;
            uint32_t bf[4][2];
#pragma unroll
            for (int nt = 0; nt < 4; nt++) {
                uint2 u = *(const uint2*)&bp[(nt * 8 + g) * 8 + tg * 2];
                bf[nt][0] = u.x; bf[nt][1] = u.y;
            }
#pragma unroll
            for (int nt = 0; nt < 4; nt++) {
                mma16(acc[0][nt], a0, bf[nt]);
                mma16(acc[1][nt], a1, bf[nt]);
            }
        }

        // all warps publish partials; xproj regs -> psm[4]
        {
            float* pp = psm + kh * (64 * PSTR);
#pragma unroll
            for (int mt = 0; mt < 2; mt++)
#pragma unroll
                for (int rr = 0; rr < 2; rr++) {
                    int row = wm * 32 + mt * 16 + rr * 8 + g;
#pragma unroll
                    for (int nt = 0; nt < 4; nt++)
                        *(float2*)&pp[row * PSTR + nt * 8 + tg * 2] =
                            make_float2(acc[mt][nt][rr * 2], acc[mt][nt][rr * 2 + 1]);
                }
            float* xd = psm + 4 * (64 * PSTR) + eb * PSTR + eu * 8;
            *(float4*)xd       = xr0;
            *(float4*)(xd + 4) = xr1;
        }
        __syncthreads();

        // epilogue: every thread handles (eb, j = 2eu, 2eu+1)
        {
            float2 gv[4];
#pragma unroll
            for (int gg = 0; gg < 4; gg++) {
                float2 s = make_float2(0.0f, 0.0f);
#pragma unroll
                for (int p = 0; p < 5; p++) {
                    float2 q = *(const float2*)&psm[p * (64 * PSTR)
                                + eb * PSTR + gg * 8 + eu * 2];
                    s.x += q.x; s.y += q.y;
                }
                gv[gg] = s;
            }
            float ig0 = sigm(gv[0].x), fg0 = sigm(gv[1].x), og0 = sigm(gv[2].x);
            float cg0 = tanh_mufu(gv[3].x);
            float c0  = fg0 * cst0 + ig0 * cg0;  cst0 = c0;
            float h0  = og0 * tanh_precise(c0);
            float ig1 = sigm(gv[0].y), fg1 = sigm(gv[1].y), og1 = sigm(gv[2].y);
            float cg1 = tanh_mufu(gv[3].y);
            float c1  = fg1 * cst1 + ig1 * cg1;  cst1 = c1;
            float h1  = og1 * tanh_precise(c1);

            __stcg(&d_hf[(t + 1) & 1][hword], h2u(h0, h1));
            if (t == SRCLEN - 1) {
                int col = cta * 8 + eu * 2;
                *(float2*)(out + eb * HIDDEN + col) = make_float2(h0, h1);
                *(float2*)(out + BATCH * HIDDEN + eb * HIDDEN + col) =
                    make_float2(c0, c1);
            }
        }

        // grid barrier: per-step counters spread over 8 addresses (16 CTAs ea),
        // warp 0 polls all 8 lane-parallel. Same semantics as proven R5 barrier.
        __syncthreads();
        if (tid == 0) {
            __threadfence();
            atomicAdd(&d_bar8[t * 8 + (cta & 7)], 1u);
        }
        if (warp == 0) {
            bool ok;
            do {
                unsigned v = (lane < 8) ? ldflag(&d_bar8[t * 8 + lane]) : 16u;
                ok = (v >= 16u);
            } while (!__all_sync(0xFFFFFFFFu, ok));
        }
        __syncthreads();
    }
}

// ---------------------------------------------------------------------------
extern "C" void kernel_launch(void* const* d_in, const int* in_sizes, int n_in,
                              void* d_out, int out_size)
{
    const int*   src = (const int*)d_in[0];
    const float* emb = (const float*)d_in[1];
    const float* Wx  = (const float*)d_in[2];
    const float* bx  = (const float*)d_in[3];
    const float* Wh  = (const float*)d_in[4];
    float*       out = (float*)d_out;

    init_kernel<<<128, 256>>>();

    cudaFuncSetAttribute(xproj_kernel, cudaFuncAttributeMaxDynamicSharedMemorySize,
                         4 * XP_BUF * 4);
    xproj_kernel<<<dim3(G4 / 128, (SRCLEN * BATCH) / 128), 256, 4 * XP_BUF * 4>>>(
        src, emb, Wx, bx);

    cudaFuncSetAttribute(lstm_kernel, cudaFuncAttributeMaxDynamicSharedMemorySize,
                         LSTM_SMEM_WORDS * 4);
    lstm_kernel<<<NCTA, 256, LSTM_SMEM_WORDS * 4>>>(Wh, out);
}

// round 8
// speedup vs baseline: 5.9492x; 1.1112x over previous
#include <cuda_runtime.h>
#include <cuda_fp16.h>
#include <math.h>
#include <stdint.h>

#define VOCAB   32000
#define EMBED   512
#define HIDDEN  1024
#define G4      4096
#define BATCH   64
#define SRCLEN  1024
#define NCTA    128

// Scratch (device globals)
__device__ float    d_xproj[(size_t)SRCLEN * BATCH * G4];   // (t,b,g) fp32
__device__ __half   d_emb16[(size_t)VOCAB * EMBED];
__device__ __half   d_wx16[(size_t)G4 * EMBED];
// h as half2 words in mma-A-fragment layout:
//   word(kt, row, tg, j) = kt*512 + row*8 + tg*2 + j ; halves k = kt*16+2tg+8j, +1
__device__ unsigned d_hf[2][64 * 512];
__device__ unsigned d_bar8[SRCLEN * 8];     // per-step spread arrival counters

// ---------------------------------------------------------------------------
__device__ __forceinline__ void mma16(float* c, const uint32_t* a, const uint32_t* b) {
    asm volatile(
        "mma.sync.aligned.m16n8k16.row.col.f32.f16.f16.f32 "
        "{%0,%1,%2,%3}, {%4,%5,%6,%7}, {%8,%9}, {%0,%1,%2,%3};"
        : "+f"(c[0]), "+f"(c[1]), "+f"(c[2]), "+f"(c[3])
        : "r"(a[0]), "r"(a[1]), "r"(a[2]), "r"(a[3]), "r"(b[0]), "r"(b[1]));
}
__device__ __forceinline__ uint32_t h2u(float x, float y) {
    __half2 h = __floats2half2_rn(x, y);
    return *(uint32_t*)&h;
}
__device__ __forceinline__ float tanh_mufu(float x) {
    float y;
    asm("tanh.approx.f32 %0, %1;" : "=f"(y) : "f"(x));
    return y;
}
// packed tanh on a float pair via MUFU f16x2 (1 MUFU op for 2 elements)
__device__ __forceinline__ float2 tanh2_f16(float ax, float ay) {
    __half2 hin = __floats2half2_rn(ax, ay);
    uint32_t ui = *(uint32_t*)&hin, uo;
    asm("tanh.approx.f16x2 %0, %1;" : "=r"(uo) : "r"(ui));
    __half2 ho = *(__half2*)&uo;
    return __half22float2(ho);
}
__device__ __forceinline__ unsigned ldflag(const unsigned* p) {
    unsigned v;
    asm volatile("ld.global.cg.u32 %0, [%1];" : "=r"(v) : "l"(p) : "memory");
    return v;
}

// ---------------------------------------------------------------------------
__global__ void init_kernel() {
    int i = blockIdx.x * blockDim.x + threadIdx.x;
    if (i < 64 * 512)   d_hf[0][i]  = 0u;
    if (i < SRCLEN * 8) d_bar8[i]   = 0u;
}
__global__ void conv_emb_kernel(const float* __restrict__ emb) {
    size_t i = ((size_t)blockIdx.x * blockDim.x + threadIdx.x) * 8;
    float4 a = *(const float4*)(emb + i);
    float4 b = *(const float4*)(emb + i + 4);
    uint4 o = make_uint4(h2u(a.x, a.y), h2u(a.z, a.w), h2u(b.x, b.y), h2u(b.z, b.w));
    *(uint4*)(d_emb16 + i) = o;
}
__global__ void conv_wx_kernel(const float* __restrict__ Wx) {
    size_t i = ((size_t)blockIdx.x * blockDim.x + threadIdx.x) * 8;
    float4 a = *(const float4*)(Wx + i);
    float4 b = *(const float4*)(Wx + i + 4);
    uint4 o = make_uint4(h2u(a.x, a.y), h2u(a.z, a.w), h2u(b.x, b.y), h2u(b.z, b.w));
    *(uint4*)(d_wx16 + i) = o;
}

// ---------------------------------------------------------------------------
// x_proj (fp16 mma): C[65536,4096] = emb16[src] @ Wx16^T + bx
// Staging now reads pre-converted fp16: 1 uint4 LDG per 8 halves, 4 STS.32.
// smem word layout unchanged: kto*XP_KW + row*8 + ((kl&7)>>1)*2 + (kl>>3).
// ---------------------------------------------------------------------------
#define XP_KW   1040
#define XP_BUF  (2 * XP_KW)

__global__ void __launch_bounds__(256, 1) xproj_kernel(
    const int* __restrict__ src, const float* __restrict__ bx)
{
    extern __shared__ uint32_t xpsm[];
    uint32_t* As = xpsm;
    uint32_t* Bs = xpsm + 2 * XP_BUF;
    __shared__ int tok[128];

    const int tid  = threadIdx.x;
    const int lane = tid & 31;
    const int warp = tid >> 5;
    const int wm   = warp & 1;
    const int wn   = warp >> 1;
    const int g    = lane >> 2;
    const int tg   = lane & 3;
    const int bm0  = blockIdx.y * 128;
    const int bn0  = blockIdx.x * 128;

    if (tid < 128) {
        int m = bm0 + tid;
        tok[tid] = src[(m & 63) * SRCLEN + (m >> 6)];
    }
    __syncthreads();

    float acc[4][4][4];
#pragma unroll
    for (int mt = 0; mt < 4; mt++)
#pragma unroll
        for (int nt = 0; nt < 4; nt++)
#pragma unroll
            for (int r = 0; r < 4; r++) acc[mt][nt][r] = 0.0f;

    const int sr2 = tid >> 2;          // row 0..63 (x2 iters)
    const int sq  = tid & 3;           // uint4 (8-half) index in 32-k chunk
    const int sbase0 = (sq >> 1) * XP_KW + (sq & 1);

    // stage chunk 0
#pragma unroll
    for (int it = 0; it < 2; it++) {
        int r = sr2 + it * 64;
        uint4 va = __ldg((const uint4*)(d_emb16 + (size_t)tok[r] * EMBED + sq * 8));
        uint4 vb = __ldg((const uint4*)(d_wx16 + (size_t)(bn0 + r) * EMBED + sq * 8));
        int base = sbase0 + r * 8;
        As[base]     = va.x; As[base + 2] = va.y;
        As[base + 4] = va.z; As[base + 6] = va.w;
        Bs[base]     = vb.x; Bs[base + 2] = vb.y;
        Bs[base + 4] = vb.z; Bs[base + 6] = vb.w;
    }
    __syncthreads();

    uint4 pa[2], pb[2];
    for (int kc = 0; kc < 16; kc++) {
        const int buf = kc & 1;
        if (kc + 1 < 16) {
#pragma unroll
            for (int it = 0; it < 2; it++) {
                int r = sr2 + it * 64;
                pa[it] = __ldg((const uint4*)(d_emb16 + (size_t)tok[r] * EMBED
                                              + (kc + 1) * 32 + sq * 8));
                pb[it] = __ldg((const uint4*)(d_wx16 + (size_t)(bn0 + r) * EMBED
                                              + (kc + 1) * 32 + sq * 8));
            }
        }
        const uint32_t* Ab = As + buf * XP_BUF;
        const uint32_t* Bb = Bs + buf * XP_BUF;
#pragma unroll
        for (int kt = 0; kt < 2; kt++) {
            const int kb = kt * XP_KW;
            uint32_t af[4][4], bf[4][2];
#pragma unroll
            for (int mt = 0; mt < 4; mt++) {
                int r0 = wm * 64 + mt * 16 + g;
                uint2 u0 = *(const uint2*)&Ab[kb + r0 * 8 + tg * 2];
                uint2 u1 = *(const uint2*)&Ab[kb + (r0 + 8) * 8 + tg * 2];
                af[mt][0] = u0.x; af[mt][2] = u0.y;
                af[mt][1] = u1.x; af[mt][3] = u1.y;
            }
#pragma unroll
            for (int nt = 0; nt < 4; nt++) {
                int n0 = wn * 32 + nt * 8 + g;
                uint2 u = *(const uint2*)&Bb[kb + n0 * 8 + tg * 2];
                bf[nt][0] = u.x; bf[nt][1] = u.y;
            }
#pragma unroll
            for (int mt = 0; mt < 4; mt++)
#pragma unroll
                for (int nt = 0; nt < 4; nt++)
                    mma16(acc[mt][nt], af[mt], bf[nt]);
        }
        __syncthreads();
        if (kc + 1 < 16) {
            uint32_t* Ad = As + (buf ^ 1) * XP_BUF;
            uint32_t* Bd = Bs + (buf ^ 1) * XP_BUF;
#pragma unroll
            for (int it = 0; it < 2; it++) {
                int r = sr2 + it * 64;
                int base = sbase0 + r * 8;
                Ad[base]     = pa[it].x; Ad[base + 2] = pa[it].y;
                Ad[base + 4] = pa[it].z; Ad[base + 6] = pa[it].w;
                Bd[base]     = pb[it].x; Bd[base + 2] = pb[it].y;
                Bd[base + 4] = pb[it].z; Bd[base + 6] = pb[it].w;
            }
            __syncthreads();
        }
    }

#pragma unroll
    for (int nt = 0; nt < 4; nt++) {
        int col = bn0 + wn * 32 + nt * 8 + tg * 2;
        float b0 = __ldg(bx + col);
        float b1 = __ldg(bx + col + 1);
#pragma unroll
        for (int mt = 0; mt < 4; mt++)
#pragma unroll
            for (int rr = 0; rr < 2; rr++) {
                int m = bm0 + wm * 64 + mt * 16 + rr * 8 + g;
                float2 v = make_float2(acc[mt][nt][rr * 2] + b0,
                                       acc[mt][nt][rr * 2 + 1] + b1);
                *(float2*)(d_xproj + (size_t)m * G4 + col) = v;
            }
    }
}

// ---------------------------------------------------------------------------
// Recurrence (fp16 mma), R8: f16x2-packed gate MUFU (6 MUFU/thread, was 12).
// Structure identical to passing R7 otherwise.
// ---------------------------------------------------------------------------
#define PSTR 40
#define LSTM_SMEM_WORDS (16384 + 5 * 64 * PSTR)    // 29184 words = 116736 B

__global__ void __launch_bounds__(256, 1) lstm_kernel(
    const float* __restrict__ Wh, float* __restrict__ out)
{
    extern __shared__ float lsm[];
    uint32_t* Bs  = (uint32_t*)lsm;                 // 16384 words (64 KB)
    float*    psm = lsm + 16384;                    // [5][64][PSTR]

    const int tid  = threadIdx.x;
    const int lane = tid & 31;
    const int warp = tid >> 5;
    const int cta  = blockIdx.x;
    const int wm   = warp & 1;
    const int kh   = warp >> 1;
    const int g    = lane >> 2;
    const int tg   = lane & 3;

    // One-time: Wh slice -> fp16 B-fragment smem
    for (int i = tid; i < 32 * HIDDEN; i += 256) {
        int lc = i >> 10;
        int k  = i & 1023;
        int grow = (lc >> 3) * HIDDEN + cta * 8 + (lc & 7);
        float w = __ldg(Wh + (size_t)grow * HIDDEN + k);
        int kl = k & 15;
        int word = (k >> 4) * 256 + lc * 8 + ((kl & 7) >> 1) * 2 + (kl >> 3);
        ((__half*)Bs)[word * 2 + (k & 1)] = __float2half_rn(w);
    }
    __syncthreads();

    const int eb = tid >> 2;        // epilogue batch row
    const int eu = tid & 3;         // epilogue col-pair (j = 2eu, 2eu+1)
    float cst0 = 0.0f, cst1 = 0.0f;

    const int aoff  = (wm * 32 + g) * 8 + tg * 2;
    const int hword = (cta >> 1) * 512 + eb * 8 + eu * 2 + (cta & 1);

    for (int t = 0; t < SRCLEN; t++) {
        // xproj gates -> registers (gate eu, cols 0..7 of this CTA, row eb)
        const float* xp = d_xproj + ((size_t)t * BATCH + eb) * G4
                          + eu * HIDDEN + cta * 8;
        float4 xr0 = __ldg((const float4*)xp);
        float4 xr1 = __ldg((const float4*)(xp + 4));

        float acc[2][4][4];
#pragma unroll
        for (int mt = 0; mt < 2; mt++)
#pragma unroll
            for (int nt = 0; nt < 4; nt++)
#pragma unroll
                for (int r = 0; r < 4; r++) acc[mt][nt][r] = 0.0f;

        const unsigned* hb = d_hf[t & 1];

#pragma unroll 4
        for (int ki = 0; ki < 16; ki++) {
            const int kt = kh * 16 + ki;
            const int kb = kt * 512;
            uint2 u00 = __ldcg((const uint2*)&hb[kb + aoff]);
            uint2 u01 = __ldcg((const uint2*)&hb[kb + aoff + 64]);
            uint2 u10 = __ldcg((const uint2*)&hb[kb + aoff + 128]);
            uint2 u11 = __ldcg((const uint2*)&hb[kb + aoff + 192]);
            uint32_t a0[4] = {u00.x, u01.x, u00.y, u01.y};
            uint32_t a1[4] = {u10.x, u11.x, u10.y, u11.y};
            const uint32_t* bp = Bs + kt * 256;
            uint32_t bf[4][2];
#pragma unroll
            for (int nt = 0; nt < 4; nt++) {
                uint2 u = *(const uint2*)&bp[(nt * 8 + g) * 8 + tg * 2];
                bf[nt][0] = u.x; bf[nt][1] = u.y;
            }
#pragma unroll
            for (int nt = 0; nt < 4; nt++) {
                mma16(acc[0][nt], a0, bf[nt]);
                mma16(acc[1][nt], a1, bf[nt]);
            }
        }

        // all warps publish partials; xproj regs -> psm[4]
        {
            float* pp = psm + kh * (64 * PSTR);
#pragma unroll
            for (int mt = 0; mt < 2; mt++)
#pragma unroll
                for (int rr = 0; rr < 2; rr++) {
                    int row = wm * 32 + mt * 16 + rr * 8 + g;
#pragma unroll
                    for (int nt = 0; nt < 4; nt++)
                        *(float2*)&pp[row * PSTR + nt * 8 + tg * 2] =
                            make_float2(acc[mt][nt][rr * 2], acc[mt][nt][rr * 2 + 1]);
                }
            float* xd = psm + 4 * (64 * PSTR) + eb * PSTR + eu * 8;
            *(float4*)xd       = xr0;
            *(float4*)(xd + 4) = xr1;
        }
        __syncthreads();

        // epilogue: every thread handles (eb, j = 2eu, 2eu+1); gates via f16x2 MUFU
        {
            float2 gv[4];
#pragma unroll
            for (int gg = 0; gg < 4; gg++) {
                float2 s = make_float2(0.0f, 0.0f);
#pragma unroll
                for (int p = 0; p < 5; p++) {
                    float2 q = *(const float2*)&psm[p * (64 * PSTR)
                                + eb * PSTR + gg * 8 + eu * 2];
                    s.x += q.x; s.y += q.y;
                }
                gv[gg] = s;
            }
            float2 ti = tanh2_f16(0.5f * gv[0].x, 0.5f * gv[0].y);
            float2 tf = tanh2_f16(0.5f * gv[1].x, 0.5f * gv[1].y);
            float2 to = tanh2_f16(0.5f * gv[2].x, 0.5f * gv[2].y);
            float2 tgg = tanh2_f16(gv[3].x, gv[3].y);
            float ig0 = fmaf(0.5f, ti.x, 0.5f), ig1 = fmaf(0.5f, ti.y, 0.5f);
            float fg0 = fmaf(0.5f, tf.x, 0.5f), fg1 = fmaf(0.5f, tf.y, 0.5f);
            float og0 = fmaf(0.5f, to.x, 0.5f), og1 = fmaf(0.5f, to.y, 0.5f);

            float c0 = fg0 * cst0 + ig0 * tgg.x;  cst0 = c0;
            float c1 = fg1 * cst1 + ig1 * tgg.y;  cst1 = c1;
            float h0 = og0 * tanh_mufu(c0);
            float h1 = og1 * tanh_mufu(c1);

            __stcg(&d_hf[(t + 1) & 1][hword], h2u(h0, h1));
            if (t == SRCLEN - 1) {
                int col = cta * 8 + eu * 2;
                *(float2*)(out + eb * HIDDEN + col) = make_float2(h0, h1);
                *(float2*)(out + BATCH * HIDDEN + eb * HIDDEN + col) =
                    make_float2(c0, c1);
            }
        }

        // grid barrier: per-step counters spread over 8 addresses (16 CTAs ea)
        __syncthreads();
        if (tid == 0) {
            __threadfence();
            atomicAdd(&d_bar8[t * 8 + (cta & 7)], 1u);
        }
        if (warp == 0) {
            bool ok;
            do {
                unsigned v = (lane < 8) ? ldflag(&d_bar8[t * 8 + lane]) : 16u;
                ok = (v >= 16u);
            } while (!__all_sync(0xFFFFFFFFu, ok));
        }
        __syncthreads();
    }
}

// ---------------------------------------------------------------------------
extern "C" void kernel_launch(void* const* d_in, const int* in_sizes, int n_in,
                              void* d_out, int out_size)
{
    const int*   src = (const int*)d_in[0];
    const float* emb = (const float*)d_in[1];
    const float* Wx  = (const float*)d_in[2];
    const float* bx  = (const float*)d_in[3];
    const float* Wh  = (const float*)d_in[4];
    float*       out = (float*)d_out;

    init_kernel<<<128, 256>>>();
    conv_emb_kernel<<<(VOCAB * EMBED / 8) / 256, 256>>>(emb);
    conv_wx_kernel<<<(G4 * EMBED / 8) / 256, 256>>>(Wx);

    cudaFuncSetAttribute(xproj_kernel, cudaFuncAttributeMaxDynamicSharedMemorySize,
                         4 * XP_BUF * 4);
    xproj_kernel<<<dim3(G4 / 128, (SRCLEN * BATCH) / 128), 256, 4 * XP_BUF * 4>>>(
        src, bx);

    cudaFuncSetAttribute(lstm_kernel, cudaFuncAttributeMaxDynamicSharedMemorySize,
                         LSTM_SMEM_WORDS * 4);
    lstm_kernel<<<NCTA, 256, LSTM_SMEM_WORDS * 4>>>(Wh, out);
}